// round 2
// baseline (speedup 1.0000x reference)
#include <cuda_runtime.h>
#include <math.h>

// ---------------- problem constants ----------------
#define BB    64
#define HH    28
#define WW    28
#define CC    384
#define WS    7
#define SHIFT 3
#define NHD   12
#define HD    32
#define HID   1536
#define NWIN  16          // windows per image (4x4)
#define NTOK  49          // tokens per window
#define TOK   50176       // B * H * W  = 64*784
#define NWINS 1024        // B * NWIN
#define ATT_SCALE 0.17677669529663687f  // 1/sqrt(32)

// ---------------- static scratch (no allocations allowed) ----------------
__device__ float g_xw [(size_t)TOK * CC];     // LN1 + shift + window partition
__device__ float g_qkv[(size_t)TOK * 3 * CC]; // qkv projection
__device__ float g_ow [(size_t)TOK * CC];     // attention output (window order)
__device__ float g_y  [(size_t)TOK * CC];     // post-attention residual (token order)
__device__ float g_ln2[(size_t)TOK * CC];     // LN2 output
__device__ float g_mid[(size_t)TOK * HID];    // fc1+gelu output
__device__ int   g_dmap[TOK];                 // windowed row -> original token row

// ---------------- LayerNorm (optionally fused shift+window gather) ----------------
// mode 1: r is a windowed row; gather source token through the cyclic-shift +
//         window-partition bijection and record it in g_dmap.
// mode 0: identity rows (plain LN).
__global__ __launch_bounds__(128) void ln_kernel(
    const float* __restrict__ x, const float* __restrict__ g,
    const float* __restrict__ b, float* __restrict__ out, int mode)
{
    int r = blockIdx.x;
    int src = r;
    if (mode == 1) {
        int win  = r / NTOK;
        int n    = r - win * NTOK;
        int bidx = win >> 4;          // / NWIN
        int widx = win & 15;
        int wi = widx >> 2, wj = widx & 3;
        int ph = n / WS, pw = n - ph * WS;
        int h = (wi * WS + ph + SHIFT) % HH;
        int w = (wj * WS + pw + SHIFT) % WW;
        src = bidx * (HH * WW) + h * WW + w;
        if (threadIdx.x == 0) g_dmap[r] = src;
    }
    const float* xr = x + (size_t)src * CC;
    int t = threadIdx.x;
    float v0 = xr[t], v1 = xr[t + 128], v2 = xr[t + 256];
    float s  = v0 + v1 + v2;
    float s2 = v0 * v0 + v1 * v1 + v2 * v2;
    #pragma unroll
    for (int o = 16; o; o >>= 1) {
        s  += __shfl_xor_sync(0xffffffffu, s,  o);
        s2 += __shfl_xor_sync(0xffffffffu, s2, o);
    }
    __shared__ float sh[4], sh2[4];
    int warp = t >> 5, lane = t & 31;
    if (lane == 0) { sh[warp] = s; sh2[warp] = s2; }
    __syncthreads();
    if (t == 0) {
        float S = sh[0] + sh[1] + sh[2] + sh[3];
        float S2 = sh2[0] + sh2[1] + sh2[2] + sh2[3];
        float mu = S * (1.0f / CC);
        float var = S2 * (1.0f / CC) - mu * mu;
        sh[0] = mu;
        sh2[0] = rsqrtf(var + 1e-5f);
    }
    __syncthreads();
    float mu = sh[0], inv = sh2[0];
    float* orow = out + (size_t)r * CC;
    orow[t]       = (v0 - mu) * inv * g[t]       + b[t];
    orow[t + 128] = (v1 - mu) * inv * g[t + 128] + b[t + 128];
    orow[t + 256] = (v2 - mu) * inv * g[t + 256] + b[t + 256];
}

// ---------------- generic tiled fp32 GEMM + fused epilogue ----------------
// C[orow, n] = act( A[r,:] @ B[:,n] + bias[n] ) (+ addend[orow, n])
// orow = rowmap ? rowmap[r] : r.   act: 0 = none, 1 = exact GELU.
// Requires M % 64 == 0, N % 64 == 0, K % 32 == 0 (true for all calls here).
#define BM 64
#define BN 64
#define BK 32
__global__ __launch_bounds__(256) void gemm_kernel(
    const float* __restrict__ A, const float* __restrict__ Bm,
    const float* __restrict__ bias, float* __restrict__ Cc,
    const float* __restrict__ addend, const int* __restrict__ rowmap,
    int M, int Nn, int K, int act)
{
    __shared__ float As[BK][BM + 1];
    __shared__ float Bs[BK][BN];
    int tile_m = blockIdx.y * BM;
    int tile_n = blockIdx.x * BN;
    int tid = threadIdx.x;
    int tr = tid >> 4, tc = tid & 15;

    float acc[4][4] = {};

    for (int k0 = 0; k0 < K; k0 += BK) {
        #pragma unroll
        for (int i = 0; i < (BM * BK) / 256; i++) {
            int e = tid + i * 256;
            int m = e >> 5;      // / BK
            int k = e & 31;
            As[k][m] = A[(size_t)(tile_m + m) * K + k0 + k];
        }
        #pragma unroll
        for (int i = 0; i < (BK * BN) / 256; i++) {
            int e = tid + i * 256;
            int k = e >> 6;      // / BN
            int n = e & 63;
            Bs[k][n] = Bm[(size_t)(k0 + k) * Nn + tile_n + n];
        }
        __syncthreads();
        #pragma unroll
        for (int kk = 0; kk < BK; kk++) {
            float a[4], bb[4];
            #pragma unroll
            for (int i = 0; i < 4; i++) a[i] = As[kk][tr * 4 + i];
            #pragma unroll
            for (int j = 0; j < 4; j++) bb[j] = Bs[kk][tc * 4 + j];
            #pragma unroll
            for (int i = 0; i < 4; i++)
                #pragma unroll
                for (int j = 0; j < 4; j++)
                    acc[i][j] = fmaf(a[i], bb[j], acc[i][j]);
        }
        __syncthreads();
    }

    #pragma unroll
    for (int i = 0; i < 4; i++) {
        int r = tile_m + tr * 4 + i;
        int orow = rowmap ? rowmap[r] : r;
        #pragma unroll
        for (int j = 0; j < 4; j++) {
            int cidx = tile_n + tc * 4 + j;
            float v = acc[i][j] + bias[cidx];
            if (act == 1) v = 0.5f * v * (1.0f + erff(v * 0.70710678118654752f));
            size_t off = (size_t)orow * Nn + cidx;
            if (addend) v += addend[off];
            Cc[off] = v;
        }
    }
}

// ---------------- windowed attention: one block per (head, window) ----------------
__global__ __launch_bounds__(256) void attn_kernel(
    const float* __restrict__ rpb, float* __restrict__ ow)
{
    int head = blockIdx.x;   // 0..11
    int win  = blockIdx.y;   // 0..1023
    __shared__ float qs[NTOK * HD];
    __shared__ float ks[NTOK * HD];
    __shared__ float vs[NTOK * HD];
    __shared__ float S[NTOK * 52];   // padded rows

    int tid = threadIdx.x;
    const float* base = g_qkv + (size_t)win * NTOK * (3 * CC);

    for (int idx = tid; idx < NTOK * HD; idx += 256) {
        int n = idx >> 5, d = idx & 31;
        const float* row = base + (size_t)n * (3 * CC) + head * HD + d;
        qs[idx] = row[0] * ATT_SCALE;
        ks[idx] = row[CC];
        vs[idx] = row[2 * CC];
    }
    __syncthreads();

    int widx = win & 15;
    int wi = widx >> 2, wj = widx & 3;

    for (int idx = tid; idx < NTOK * NTOK; idx += 256) {
        int n = idx / NTOK, m = idx - n * NTOK;
        float dot = 0.0f;
        #pragma unroll
        for (int d = 0; d < HD; d++) dot += qs[n * HD + d] * ks[m * HD + d];
        int in_ = n / WS, jn = n - in_ * WS;
        int im  = m / WS, jm = m - im * WS;
        // relative position bias
        int rel = (in_ - im + WS - 1) * (2 * WS - 1) + (jn - jm + WS - 1);
        dot += rpb[rel * NHD + head];
        // shift mask: region id in the shifted image
        int hn = wi * WS + in_, wn = wj * WS + jn;
        int hm = wi * WS + im,  wm = wj * WS + jm;
        int vn = (hn < HH - WS ? 0 : (hn < HH - SHIFT ? 1 : 2)) * 3
               + (wn < WW - WS ? 0 : (wn < WW - SHIFT ? 1 : 2));
        int vm = (hm < HH - WS ? 0 : (hm < HH - SHIFT ? 1 : 2)) * 3
               + (wm < WW - WS ? 0 : (wm < WW - SHIFT ? 1 : 2));
        if (vn != vm) dot -= 100.0f;
        S[n * 52 + m] = dot;
    }
    __syncthreads();

    // softmax: one warp per row, rows strided by 8
    int warp = tid >> 5, lane = tid & 31;
    for (int n = warp; n < NTOK; n += 8) {
        float mx = -1e30f;
        for (int m = lane; m < NTOK; m += 32) mx = fmaxf(mx, S[n * 52 + m]);
        #pragma unroll
        for (int o = 16; o; o >>= 1) mx = fmaxf(mx, __shfl_xor_sync(0xffffffffu, mx, o));
        float sum = 0.0f;
        for (int m = lane; m < NTOK; m += 32) {
            float e = __expf(S[n * 52 + m] - mx);
            S[n * 52 + m] = e;
            sum += e;
        }
        #pragma unroll
        for (int o = 16; o; o >>= 1) sum += __shfl_xor_sync(0xffffffffu, sum, o);
        float inv = 1.0f / sum;
        for (int m = lane; m < NTOK; m += 32) S[n * 52 + m] *= inv;
    }
    __syncthreads();

    for (int idx = tid; idx < NTOK * HD; idx += 256) {
        int n = idx >> 5, d = idx & 31;
        float s = 0.0f;
        #pragma unroll
        for (int m = 0; m < NTOK; m++) s += S[n * 52 + m] * vs[m * HD + d];
        ow[((size_t)win * NTOK + n) * CC + head * HD + d] = s;
    }
}

// ---------------- launch ----------------
extern "C" void kernel_launch(void* const* d_in, const int* in_sizes, int n_in,
                              void* d_out, int out_size)
{
    const float* x      = (const float*)d_in[0];
    const float* qkv_w  = (const float*)d_in[1];
    const float* qkv_b  = (const float*)d_in[2];
    const float* proj_w = (const float*)d_in[3];
    const float* proj_b = (const float*)d_in[4];
    const float* rpb    = (const float*)d_in[5];
    const float* n1g    = (const float*)d_in[6];
    const float* n1b    = (const float*)d_in[7];
    const float* n2g    = (const float*)d_in[8];
    const float* n2b    = (const float*)d_in[9];
    const float* fc1_w  = (const float*)d_in[10];
    const float* fc1_b  = (const float*)d_in[11];
    const float* fc2_w  = (const float*)d_in[12];
    const float* fc2_b  = (const float*)d_in[13];
    float* out = (float*)d_out;

    float *xw, *qkv, *ow, *y, *ln2, *mid; int* dmap;
    cudaGetSymbolAddress((void**)&xw,   g_xw);
    cudaGetSymbolAddress((void**)&qkv,  g_qkv);
    cudaGetSymbolAddress((void**)&ow,   g_ow);
    cudaGetSymbolAddress((void**)&y,    g_y);
    cudaGetSymbolAddress((void**)&ln2,  g_ln2);
    cudaGetSymbolAddress((void**)&mid,  g_mid);
    cudaGetSymbolAddress((void**)&dmap, g_dmap);

    // 1. LN1 + cyclic shift + window partition (records token map)
    ln_kernel<<<TOK, 128>>>(x, n1g, n1b, xw, 1);

    // 2. QKV projection: (50176,384) @ (384,1152)
    gemm_kernel<<<dim3((3 * CC) / BN, TOK / BM), 256>>>(
        xw, qkv_w, qkv_b, qkv, nullptr, nullptr, TOK, 3 * CC, CC, 0);

    // 3. Windowed attention
    attn_kernel<<<dim3(NHD, NWINS), 256>>>(rpb, ow);

    // 4. Output projection + window-reverse + un-shift + residual (scatter via dmap)
    gemm_kernel<<<dim3(CC / BN, TOK / BM), 256>>>(
        ow, proj_w, proj_b, y, x, dmap, TOK, CC, CC, 0);

    // 5. LN2
    ln_kernel<<<TOK, 128>>>(y, n2g, n2b, ln2, 0);

    // 6. FC1 + exact GELU: (50176,384) @ (384,1536)
    gemm_kernel<<<dim3(HID / BN, TOK / BM), 256>>>(
        ln2, fc1_w, fc1_b, mid, nullptr, nullptr, TOK, HID, CC, 1);

    // 7. FC2 + residual: (50176,1536) @ (1536,384)
    gemm_kernel<<<dim3(CC / BN, TOK / BM), 256>>>(
        mid, fc2_w, fc2_b, out, y, nullptr, TOK, CC, HID, 0);
}

// round 3
// speedup vs baseline: 2.4348x; 2.4348x over previous
#include <cuda_runtime.h>
#include <math.h>

// ---------------- problem constants ----------------
#define BB    64
#define HH    28
#define WW    28
#define CC    384
#define WS    7
#define SHIFT 3
#define NHD   12
#define HD    32
#define HID   1536
#define NWIN  16
#define NTOK  49
#define TOK   50176
#define NWINS 1024
#define ATT_SCALE 0.17677669529663687f

// ---------------- static scratch ----------------
__device__ float g_xw [(size_t)TOK * CC];
__device__ float g_qkv[(size_t)TOK * 3 * CC];
__device__ float g_ow [(size_t)TOK * CC];
__device__ float g_y  [(size_t)TOK * CC];
__device__ float g_ln2[(size_t)TOK * CC];
__device__ float g_mid[(size_t)TOK * HID];
__device__ int   g_dmap[TOK];

__device__ __forceinline__ float to_tf32(float x) {
    float r;
    asm("cvt.rna.tf32.f32 %0, %1;" : "=f"(r) : "f"(x));
    return r;
}

// ---------------- LayerNorm (mode 1 fuses shift + window partition) ----------------
__global__ __launch_bounds__(128) void ln_kernel(
    const float* __restrict__ x, const float* __restrict__ g,
    const float* __restrict__ b, float* __restrict__ out, int mode)
{
    int r = blockIdx.x;
    int src = r;
    if (mode == 1) {
        int win  = r / NTOK;
        int n    = r - win * NTOK;
        int bidx = win >> 4;
        int widx = win & 15;
        int wi = widx >> 2, wj = widx & 3;
        int ph = n / WS, pw = n - ph * WS;
        int h = (wi * WS + ph + SHIFT) % HH;
        int w = (wj * WS + pw + SHIFT) % WW;
        src = bidx * (HH * WW) + h * WW + w;
        if (threadIdx.x == 0) g_dmap[r] = src;
    }
    const float* xr = x + (size_t)src * CC;
    int t = threadIdx.x;
    float v0 = xr[t], v1 = xr[t + 128], v2 = xr[t + 256];
    float s  = v0 + v1 + v2;
    float s2 = v0 * v0 + v1 * v1 + v2 * v2;
    #pragma unroll
    for (int o = 16; o; o >>= 1) {
        s  += __shfl_xor_sync(0xffffffffu, s,  o);
        s2 += __shfl_xor_sync(0xffffffffu, s2, o);
    }
    __shared__ float sh[4], sh2[4];
    int warp = t >> 5, lane = t & 31;
    if (lane == 0) { sh[warp] = s; sh2[warp] = s2; }
    __syncthreads();
    if (t == 0) {
        float S = sh[0] + sh[1] + sh[2] + sh[3];
        float S2 = sh2[0] + sh2[1] + sh2[2] + sh2[3];
        float mu = S * (1.0f / CC);
        float var = S2 * (1.0f / CC) - mu * mu;
        sh[0] = mu;
        sh2[0] = rsqrtf(var + 1e-5f);
    }
    __syncthreads();
    float mu = sh[0], inv = sh2[0];
    float* orow = out + (size_t)r * CC;
    orow[t]       = (v0 - mu) * inv * g[t]       + b[t];
    orow[t + 128] = (v1 - mu) * inv * g[t + 128] + b[t + 128];
    orow[t + 256] = (v2 - mu) * inv * g[t + 256] + b[t + 256];
}

// ---------------- tf32 tensor-core GEMM (mma.sync m16n8k8) ----------------
// Block tile 128x128, BK=16, 8 warps (2 m x 4 n), warp tile 64x32.
// A: row-major [M,K]; B: row-major [K,N]. Epilogue: bias, optional exact GELU,
// optional row remap (scatter) and addend (residual).
#define GBM 128
#define GBN 128
#define GBK 16
#define AST 20    // A smem row stride (floats): 16 + 4 pad
#define BST 136   // B smem row stride (floats): 128 + 8 pad

__global__ __launch_bounds__(256, 2) void mma_gemm(
    const float* __restrict__ A, const float* __restrict__ Bm,
    const float* __restrict__ bias, float* __restrict__ Cc,
    const float* __restrict__ addend, const int* __restrict__ rowmap,
    int M, int Nn, int K, int act)
{
    __shared__ __align__(16) float As[2][GBM * AST];   // [m][k]
    __shared__ __align__(16) float Bs[2][GBK * BST];   // [k][n]

    int tid  = threadIdx.x;
    int warp = tid >> 5, lane = tid & 31;
    int g    = lane >> 2, t4 = lane & 3;
    int wm   = warp >> 2, wn = warp & 3;   // 2 x 4
    int tile_m = blockIdx.y * GBM;
    int tile_n = blockIdx.x * GBN;

    float acc[4][4][4];
    #pragma unroll
    for (int i = 0; i < 4; i++)
        #pragma unroll
        for (int j = 0; j < 4; j++)
            #pragma unroll
            for (int q = 0; q < 4; q++) acc[i][j][q] = 0.0f;

    // staging registers
    float4 stA[2], stB[2];

    const int am[2] = { tid >> 2, (tid + 256) >> 2 };
    const int ak[2] = { (tid & 3) * 4, ((tid + 256) & 3) * 4 };
    const int bk[2] = { tid >> 5, (tid + 256) >> 5 };
    const int bn[2] = { (tid & 31) * 4, ((tid + 256) & 31) * 4 };

    auto loadG = [&](int k0) {
        #pragma unroll
        for (int i = 0; i < 2; i++)
            stA[i] = *(const float4*)&A[(size_t)(tile_m + am[i]) * K + k0 + ak[i]];
        #pragma unroll
        for (int i = 0; i < 2; i++)
            stB[i] = *(const float4*)&Bm[(size_t)(k0 + bk[i]) * Nn + tile_n + bn[i]];
    };
    auto storeS = [&](int buf) {
        #pragma unroll
        for (int i = 0; i < 2; i++) {
            float4 c;
            c.x = to_tf32(stA[i].x); c.y = to_tf32(stA[i].y);
            c.z = to_tf32(stA[i].z); c.w = to_tf32(stA[i].w);
            *(float4*)&As[buf][am[i] * AST + ak[i]] = c;
        }
        #pragma unroll
        for (int i = 0; i < 2; i++) {
            float4 c;
            c.x = to_tf32(stB[i].x); c.y = to_tf32(stB[i].y);
            c.z = to_tf32(stB[i].z); c.w = to_tf32(stB[i].w);
            *(float4*)&Bs[buf][bk[i] * BST + bn[i]] = c;
        }
    };

    loadG(0);
    storeS(0);
    __syncthreads();

    int nk = K / GBK;
    for (int it = 0; it < nk; it++) {
        int buf = it & 1;
        bool more = (it + 1) < nk;
        if (more) loadG((it + 1) * GBK);

        #pragma unroll
        for (int ks = 0; ks < 2; ks++) {
            int kb = ks * 8;
            unsigned a[4][4], bfr[4][2];
            #pragma unroll
            for (int mt = 0; mt < 4; mt++) {
                int mrow = wm * 64 + mt * 16;
                a[mt][0] = __float_as_uint(As[buf][(mrow + g)     * AST + kb + t4]);
                a[mt][1] = __float_as_uint(As[buf][(mrow + g + 8) * AST + kb + t4]);
                a[mt][2] = __float_as_uint(As[buf][(mrow + g)     * AST + kb + t4 + 4]);
                a[mt][3] = __float_as_uint(As[buf][(mrow + g + 8) * AST + kb + t4 + 4]);
            }
            #pragma unroll
            for (int nt = 0; nt < 4; nt++) {
                int ncol = wn * 32 + nt * 8;
                bfr[nt][0] = __float_as_uint(Bs[buf][(kb + t4)     * BST + ncol + g]);
                bfr[nt][1] = __float_as_uint(Bs[buf][(kb + t4 + 4) * BST + ncol + g]);
            }
            #pragma unroll
            for (int mt = 0; mt < 4; mt++)
                #pragma unroll
                for (int nt = 0; nt < 4; nt++) {
                    asm volatile(
                        "mma.sync.aligned.m16n8k8.row.col.f32.tf32.tf32.f32 "
                        "{%0,%1,%2,%3},{%4,%5,%6,%7},{%8,%9},{%0,%1,%2,%3};"
                        : "+f"(acc[mt][nt][0]), "+f"(acc[mt][nt][1]),
                          "+f"(acc[mt][nt][2]), "+f"(acc[mt][nt][3])
                        : "r"(a[mt][0]), "r"(a[mt][1]), "r"(a[mt][2]), "r"(a[mt][3]),
                          "r"(bfr[nt][0]), "r"(bfr[nt][1]));
                }
        }

        if (more) {
            storeS(buf ^ 1);
            __syncthreads();
        }
    }

    // epilogue
    #pragma unroll
    for (int mt = 0; mt < 4; mt++) {
        int r0 = tile_m + wm * 64 + mt * 16 + g;
        int r1 = r0 + 8;
        int o0 = rowmap ? rowmap[r0] : r0;
        int o1 = rowmap ? rowmap[r1] : r1;
        #pragma unroll
        for (int nt = 0; nt < 4; nt++) {
            int c0 = tile_n + wn * 32 + nt * 8 + 2 * t4;
            #pragma unroll
            for (int q = 0; q < 4; q++) {
                int row = (q < 2) ? o0 : o1;
                int col = c0 + (q & 1);
                float v = acc[mt][nt][q] + bias[col];
                if (act == 1) v = 0.5f * v * (1.0f + erff(v * 0.70710678118654752f));
                size_t off = (size_t)row * Nn + col;
                if (addend) v += addend[off];
                Cc[off] = v;
            }
        }
    }
}

// ---------------- windowed attention ----------------
__global__ __launch_bounds__(256) void attn_kernel(
    const float* __restrict__ rpb, float* __restrict__ ow)
{
    int head = blockIdx.x;
    int win  = blockIdx.y;
    __shared__ __align__(16) float qs[NTOK * HD];
    __shared__ __align__(16) float ks[NTOK * HD];
    __shared__ __align__(16) float vs[NTOK * HD];
    __shared__ float S[NTOK * 52];

    int tid = threadIdx.x;
    const float* base = g_qkv + (size_t)win * NTOK * (3 * CC);

    for (int idx = tid; idx < NTOK * HD; idx += 256) {
        int n = idx >> 5, d = idx & 31;
        const float* row = base + (size_t)n * (3 * CC) + head * HD + d;
        qs[idx] = row[0] * ATT_SCALE;
        ks[idx] = row[CC];
        vs[idx] = row[2 * CC];
    }
    __syncthreads();

    int widx = win & 15;
    int wi = widx >> 2, wj = widx & 3;

    // QK^T + bias + mask: thread (n, ms) with q row in registers
    if (tid < 245) {
        int n  = tid / 5;
        int ms = tid - n * 5;
        float4 q[8];
        const float4* q4 = (const float4*)&qs[n * HD];
        #pragma unroll
        for (int i = 0; i < 8; i++) q[i] = q4[i];

        int in_ = n / WS, jn = n - in_ * WS;
        int hn = wi * WS + in_, wn_ = wj * WS + jn;
        int vn = (hn < HH - WS ? 0 : (hn < HH - SHIFT ? 1 : 2)) * 3
               + (wn_ < WW - WS ? 0 : (wn_ < WW - SHIFT ? 1 : 2));

        for (int m = ms; m < NTOK; m += 5) {
            const float4* k4 = (const float4*)&ks[m * HD];
            float dot = 0.0f;
            #pragma unroll
            for (int i = 0; i < 8; i++) {
                float4 kk = k4[i];
                dot += q[i].x * kk.x + q[i].y * kk.y + q[i].z * kk.z + q[i].w * kk.w;
            }
            int im = m / WS, jm = m - im * WS;
            int rel = (in_ - im + WS - 1) * (2 * WS - 1) + (jn - jm + WS - 1);
            dot += rpb[rel * NHD + head];
            int hm = wi * WS + im, wm = wj * WS + jm;
            int vm = (hm < HH - WS ? 0 : (hm < HH - SHIFT ? 1 : 2)) * 3
                   + (wm < WW - WS ? 0 : (wm < WW - SHIFT ? 1 : 2));
            if (vn != vm) dot -= 100.0f;
            S[n * 52 + m] = dot;
        }
    }
    __syncthreads();

    // softmax: one warp per row
    int warp = tid >> 5, lane = tid & 31;
    for (int n = warp; n < NTOK; n += 8) {
        float mx = -1e30f;
        for (int m = lane; m < NTOK; m += 32) mx = fmaxf(mx, S[n * 52 + m]);
        #pragma unroll
        for (int o = 16; o; o >>= 1) mx = fmaxf(mx, __shfl_xor_sync(0xffffffffu, mx, o));
        float sum = 0.0f;
        for (int m = lane; m < NTOK; m += 32) {
            float e = __expf(S[n * 52 + m] - mx);
            S[n * 52 + m] = e;
            sum += e;
        }
        #pragma unroll
        for (int o = 16; o; o >>= 1) sum += __shfl_xor_sync(0xffffffffu, sum, o);
        float inv = 1.0f / sum;
        for (int m = lane; m < NTOK; m += 32) S[n * 52 + m] *= inv;
    }
    __syncthreads();

    // P @ V: thread (n, d-quad), float4 V loads, P broadcast
    const float4* v4 = (const float4*)vs;
    for (int idx = tid; idx < NTOK * 8; idx += 256) {
        int n = idx >> 3, dq = idx & 7;
        float4 s4 = make_float4(0.f, 0.f, 0.f, 0.f);
        for (int m = 0; m < NTOK; m++) {
            float p = S[n * 52 + m];
            float4 v = v4[m * 8 + dq];
            s4.x += p * v.x; s4.y += p * v.y; s4.z += p * v.z; s4.w += p * v.w;
        }
        float* orow = ow + ((size_t)win * NTOK + n) * CC + head * HD + dq * 4;
        orow[0] = s4.x; orow[1] = s4.y; orow[2] = s4.z; orow[3] = s4.w;
    }
}

// ---------------- launch ----------------
extern "C" void kernel_launch(void* const* d_in, const int* in_sizes, int n_in,
                              void* d_out, int out_size)
{
    const float* x      = (const float*)d_in[0];
    const float* qkv_w  = (const float*)d_in[1];
    const float* qkv_b  = (const float*)d_in[2];
    const float* proj_w = (const float*)d_in[3];
    const float* proj_b = (const float*)d_in[4];
    const float* rpb    = (const float*)d_in[5];
    const float* n1g    = (const float*)d_in[6];
    const float* n1b    = (const float*)d_in[7];
    const float* n2g    = (const float*)d_in[8];
    const float* n2b    = (const float*)d_in[9];
    const float* fc1_w  = (const float*)d_in[10];
    const float* fc1_b  = (const float*)d_in[11];
    const float* fc2_w  = (const float*)d_in[12];
    const float* fc2_b  = (const float*)d_in[13];
    float* out = (float*)d_out;

    float *xw, *qkv, *ow, *y, *ln2, *mid; int* dmap;
    cudaGetSymbolAddress((void**)&xw,   g_xw);
    cudaGetSymbolAddress((void**)&qkv,  g_qkv);
    cudaGetSymbolAddress((void**)&ow,   g_ow);
    cudaGetSymbolAddress((void**)&y,    g_y);
    cudaGetSymbolAddress((void**)&ln2,  g_ln2);
    cudaGetSymbolAddress((void**)&mid,  g_mid);
    cudaGetSymbolAddress((void**)&dmap, g_dmap);

    // 1. LN1 + shift + window partition
    ln_kernel<<<TOK, 128>>>(x, n1g, n1b, xw, 1);

    // 2. QKV: (50176,384) @ (384,1152)
    mma_gemm<<<dim3((3 * CC) / GBN, TOK / GBM), 256>>>(
        xw, qkv_w, qkv_b, qkv, nullptr, nullptr, TOK, 3 * CC, CC, 0);

    // 3. Windowed attention
    attn_kernel<<<dim3(NHD, NWINS), 256>>>(rpb, ow);

    // 4. Proj + window reverse + residual
    mma_gemm<<<dim3(CC / GBN, TOK / GBM), 256>>>(
        ow, proj_w, proj_b, y, x, dmap, TOK, CC, CC, 0);

    // 5. LN2
    ln_kernel<<<TOK, 128>>>(y, n2g, n2b, ln2, 0);

    // 6. FC1 + GELU: (50176,384) @ (384,1536)
    mma_gemm<<<dim3(HID / GBN, TOK / GBM), 256>>>(
        ln2, fc1_w, fc1_b, mid, nullptr, nullptr, TOK, HID, CC, 1);

    // 7. FC2 + residual: (50176,1536) @ (1536,384)
    mma_gemm<<<dim3(CC / GBN, TOK / GBM), 256>>>(
        mid, fc2_w, fc2_b, out, y, nullptr, TOK, CC, HID, 0);
}

// round 4
// speedup vs baseline: 2.7290x; 1.1208x over previous
#include <cuda_runtime.h>
#include <math.h>
#include <stdint.h>

// ---------------- problem constants ----------------
#define BB    64
#define HH    28
#define WW    28
#define CC    384
#define WS    7
#define SHIFT 3
#define NHD   12
#define HD    32
#define HID   1536
#define NWIN  16
#define NTOK  49
#define TOK   50176
#define NWINS 1024
#define ATT_SCALE 0.17677669529663687f

// ---------------- static scratch ----------------
__device__ float g_xw [(size_t)TOK * CC];
__device__ float g_qkv[(size_t)TOK * 3 * CC];
__device__ float g_ow [(size_t)TOK * CC];
__device__ float g_y  [(size_t)TOK * CC];
__device__ float g_ln2[(size_t)TOK * CC];
__device__ float g_mid[(size_t)TOK * HID];
__device__ int   g_dmap[TOK];

// ---------------- LayerNorm (mode 1 fuses shift + window partition) ----------------
__global__ __launch_bounds__(128) void ln_kernel(
    const float* __restrict__ x, const float* __restrict__ g,
    const float* __restrict__ b, float* __restrict__ out, int mode)
{
    int r = blockIdx.x;
    int src = r;
    if (mode == 1) {
        int win  = r / NTOK;
        int n    = r - win * NTOK;
        int bidx = win >> 4;
        int widx = win & 15;
        int wi = widx >> 2, wj = widx & 3;
        int ph = n / WS, pw = n - ph * WS;
        int h = (wi * WS + ph + SHIFT) % HH;
        int w = (wj * WS + pw + SHIFT) % WW;
        src = bidx * (HH * WW) + h * WW + w;
        if (threadIdx.x == 0) g_dmap[r] = src;
    }
    const float* xr = x + (size_t)src * CC;
    int t = threadIdx.x;
    float v0 = xr[t], v1 = xr[t + 128], v2 = xr[t + 256];
    float s  = v0 + v1 + v2;
    float s2 = v0 * v0 + v1 * v1 + v2 * v2;
    #pragma unroll
    for (int o = 16; o; o >>= 1) {
        s  += __shfl_xor_sync(0xffffffffu, s,  o);
        s2 += __shfl_xor_sync(0xffffffffu, s2, o);
    }
    __shared__ float sh[4], sh2[4];
    int warp = t >> 5, lane = t & 31;
    if (lane == 0) { sh[warp] = s; sh2[warp] = s2; }
    __syncthreads();
    if (t == 0) {
        float S = sh[0] + sh[1] + sh[2] + sh[3];
        float S2 = sh2[0] + sh2[1] + sh2[2] + sh2[3];
        float mu = S * (1.0f / CC);
        float var = S2 * (1.0f / CC) - mu * mu;
        sh[0] = mu;
        sh2[0] = rsqrtf(var + 1e-5f);
    }
    __syncthreads();
    float mu = sh[0], inv = sh2[0];
    float* orow = out + (size_t)r * CC;
    orow[t]       = (v0 - mu) * inv * g[t]       + b[t];
    orow[t + 128] = (v1 - mu) * inv * g[t + 128] + b[t + 128];
    orow[t + 256] = (v2 - mu) * inv * g[t + 256] + b[t + 256];
}

// ---------------- tf32 tensor-core GEMM, 4-stage cp.async pipeline ----------------
// Block tile 128x128, GBK=16, 8 warps (2m x 4n), warp tile 64x32.
// fp32 operands stored raw in smem; HMMA.tf32 truncates mantissa in HW (RZ).
#define GBM 128
#define GBN 128
#define GBK 16
#define AST 20          // A smem row stride (floats): 16 + 4 pad  (conflict-free frags)
#define BST 136         // B smem row stride (floats): 128 + 8 pad
#define STAGES 4
#define A_STG (GBM * AST)   // 2560 floats per stage
#define B_STG (GBK * BST)   // 2176 floats per stage
#define SMEM_BYTES (STAGES * (A_STG + B_STG) * 4)   // 75776

__device__ __forceinline__ void cp16(uint32_t s, const void* g) {
    asm volatile("cp.async.cg.shared.global [%0], [%1], 16;" :: "r"(s), "l"(g));
}

__global__ __launch_bounds__(256, 2) void mma_gemm(
    const float* __restrict__ A, const float* __restrict__ Bm,
    const float* __restrict__ bias, float* __restrict__ Cc,
    const float* __restrict__ addend, const int* __restrict__ rowmap,
    int M, int Nn, int K, int act)
{
    extern __shared__ float sm[];
    float* As = sm;
    float* Bs = sm + STAGES * A_STG;
    uint32_t as_base = (uint32_t)__cvta_generic_to_shared(As);
    uint32_t bs_base = (uint32_t)__cvta_generic_to_shared(Bs);

    int tid  = threadIdx.x;
    int warp = tid >> 5, lane = tid & 31;
    int g    = lane >> 2, t4 = lane & 3;
    int wm   = warp >> 2, wn = warp & 3;
    int tile_m = blockIdx.y * GBM;
    int tile_n = blockIdx.x * GBN;
    int nk = K / GBK;

    // per-thread copy coordinates (2 x 16B chunks each for A and B)
    int amr[2], akc[2], bkr[2], bnc[2];
    #pragma unroll
    for (int i = 0; i < 2; i++) {
        int c = tid + i * 256;
        amr[i] = c >> 2;  akc[i] = (c & 3) * 4;
        bkr[i] = c >> 5;  bnc[i] = (c & 31) * 4;
    }

    auto issue = [&](int tile) {
        int k0 = tile * GBK;
        int s  = tile & (STAGES - 1);
        uint32_t a0 = as_base + (uint32_t)(s * A_STG) * 4u;
        uint32_t b0 = bs_base + (uint32_t)(s * B_STG) * 4u;
        #pragma unroll
        for (int i = 0; i < 2; i++)
            cp16(a0 + (uint32_t)(amr[i] * AST + akc[i]) * 4u,
                 &A[(size_t)(tile_m + amr[i]) * K + k0 + akc[i]]);
        #pragma unroll
        for (int i = 0; i < 2; i++)
            cp16(b0 + (uint32_t)(bkr[i] * BST + bnc[i]) * 4u,
                 &Bm[(size_t)(k0 + bkr[i]) * Nn + tile_n + bnc[i]]);
        asm volatile("cp.async.commit_group;");
    };

    float acc[4][4][4];
    #pragma unroll
    for (int i = 0; i < 4; i++)
        #pragma unroll
        for (int j = 0; j < 4; j++)
            #pragma unroll
            for (int q = 0; q < 4; q++) acc[i][j][q] = 0.0f;

    #pragma unroll
    for (int s = 0; s < STAGES - 1; s++) issue(s);

    for (int it = 0; it < nk; it++) {
        asm volatile("cp.async.wait_group %0;" :: "n"(STAGES - 2));
        __syncthreads();
        int s = it & (STAGES - 1);
        const float* Ab = As + s * A_STG;
        const float* Bb = Bs + s * B_STG;
        int nxt = it + STAGES - 1;
        if (nxt < nk) issue(nxt);
        else asm volatile("cp.async.commit_group;");

        #pragma unroll
        for (int ks = 0; ks < 2; ks++) {
            int kb = ks * 8;
            unsigned a[4][4], bfr[4][2];
            #pragma unroll
            for (int mt = 0; mt < 4; mt++) {
                int mrow = wm * 64 + mt * 16;
                a[mt][0] = __float_as_uint(Ab[(mrow + g)     * AST + kb + t4]);
                a[mt][1] = __float_as_uint(Ab[(mrow + g + 8) * AST + kb + t4]);
                a[mt][2] = __float_as_uint(Ab[(mrow + g)     * AST + kb + t4 + 4]);
                a[mt][3] = __float_as_uint(Ab[(mrow + g + 8) * AST + kb + t4 + 4]);
            }
            #pragma unroll
            for (int nt = 0; nt < 4; nt++) {
                int ncol = wn * 32 + nt * 8;
                bfr[nt][0] = __float_as_uint(Bb[(kb + t4)     * BST + ncol + g]);
                bfr[nt][1] = __float_as_uint(Bb[(kb + t4 + 4) * BST + ncol + g]);
            }
            #pragma unroll
            for (int mt = 0; mt < 4; mt++)
                #pragma unroll
                for (int nt = 0; nt < 4; nt++) {
                    asm volatile(
                        "mma.sync.aligned.m16n8k8.row.col.f32.tf32.tf32.f32 "
                        "{%0,%1,%2,%3},{%4,%5,%6,%7},{%8,%9},{%0,%1,%2,%3};"
                        : "+f"(acc[mt][nt][0]), "+f"(acc[mt][nt][1]),
                          "+f"(acc[mt][nt][2]), "+f"(acc[mt][nt][3])
                        : "r"(a[mt][0]), "r"(a[mt][1]), "r"(a[mt][2]), "r"(a[mt][3]),
                          "r"(bfr[nt][0]), "r"(bfr[nt][1]));
                }
        }
    }

    // epilogue
    #pragma unroll
    for (int mt = 0; mt < 4; mt++) {
        int r0 = tile_m + wm * 64 + mt * 16 + g;
        int r1 = r0 + 8;
        int o0 = rowmap ? rowmap[r0] : r0;
        int o1 = rowmap ? rowmap[r1] : r1;
        #pragma unroll
        for (int nt = 0; nt < 4; nt++) {
            int c0 = tile_n + wn * 32 + nt * 8 + 2 * t4;
            #pragma unroll
            for (int q = 0; q < 4; q++) {
                int row = (q < 2) ? o0 : o1;
                int col = c0 + (q & 1);
                float v = acc[mt][nt][q] + bias[col];
                if (act == 1) v = 0.5f * v * (1.0f + erff(v * 0.70710678118654752f));
                size_t off = (size_t)row * Nn + col;
                if (addend) v += addend[off];
                Cc[off] = v;
            }
        }
    }
}

// ---------------- windowed attention ----------------
__global__ __launch_bounds__(256) void attn_kernel(
    const float* __restrict__ rpb, float* __restrict__ ow)
{
    int head = blockIdx.x;
    int win  = blockIdx.y;
    __shared__ __align__(16) float qs[NTOK * HD];
    __shared__ __align__(16) float ks[NTOK * HD];
    __shared__ __align__(16) float vs[NTOK * HD];
    __shared__ float S[NTOK * 52];

    int tid = threadIdx.x;
    const float* base = g_qkv + (size_t)win * NTOK * (3 * CC);

    for (int idx = tid; idx < NTOK * HD; idx += 256) {
        int n = idx >> 5, d = idx & 31;
        const float* row = base + (size_t)n * (3 * CC) + head * HD + d;
        qs[idx] = row[0] * ATT_SCALE;
        ks[idx] = row[CC];
        vs[idx] = row[2 * CC];
    }
    __syncthreads();

    int widx = win & 15;
    int wi = widx >> 2, wj = widx & 3;

    if (tid < 245) {
        int n  = tid / 5;
        int ms = tid - n * 5;
        float4 q[8];
        const float4* q4 = (const float4*)&qs[n * HD];
        #pragma unroll
        for (int i = 0; i < 8; i++) q[i] = q4[i];

        int in_ = n / WS, jn = n - in_ * WS;
        int hn = wi * WS + in_, wn_ = wj * WS + jn;
        int vn = (hn < HH - WS ? 0 : (hn < HH - SHIFT ? 1 : 2)) * 3
               + (wn_ < WW - WS ? 0 : (wn_ < WW - SHIFT ? 1 : 2));

        for (int m = ms; m < NTOK; m += 5) {
            const float4* k4 = (const float4*)&ks[m * HD];
            float dot = 0.0f;
            #pragma unroll
            for (int i = 0; i < 8; i++) {
                float4 kk = k4[i];
                dot += q[i].x * kk.x + q[i].y * kk.y + q[i].z * kk.z + q[i].w * kk.w;
            }
            int im = m / WS, jm = m - im * WS;
            int rel = (in_ - im + WS - 1) * (2 * WS - 1) + (jn - jm + WS - 1);
            dot += rpb[rel * NHD + head];
            int hm = wi * WS + im, wm = wj * WS + jm;
            int vm = (hm < HH - WS ? 0 : (hm < HH - SHIFT ? 1 : 2)) * 3
                   + (wm < WW - WS ? 0 : (wm < WW - SHIFT ? 1 : 2));
            if (vn != vm) dot -= 100.0f;
            S[n * 52 + m] = dot;
        }
    }
    __syncthreads();

    int warp = tid >> 5, lane = tid & 31;
    for (int n = warp; n < NTOK; n += 8) {
        float mx = -1e30f;
        for (int m = lane; m < NTOK; m += 32) mx = fmaxf(mx, S[n * 52 + m]);
        #pragma unroll
        for (int o = 16; o; o >>= 1) mx = fmaxf(mx, __shfl_xor_sync(0xffffffffu, mx, o));
        float sum = 0.0f;
        for (int m = lane; m < NTOK; m += 32) {
            float e = __expf(S[n * 52 + m] - mx);
            S[n * 52 + m] = e;
            sum += e;
        }
        #pragma unroll
        for (int o = 16; o; o >>= 1) sum += __shfl_xor_sync(0xffffffffu, sum, o);
        float inv = 1.0f / sum;
        for (int m = lane; m < NTOK; m += 32) S[n * 52 + m] *= inv;
    }
    __syncthreads();

    const float4* v4 = (const float4*)vs;
    for (int idx = tid; idx < NTOK * 8; idx += 256) {
        int n = idx >> 3, dq = idx & 7;
        float4 s4 = make_float4(0.f, 0.f, 0.f, 0.f);
        for (int m = 0; m < NTOK; m++) {
            float p = S[n * 52 + m];
            float4 v = v4[m * 8 + dq];
            s4.x += p * v.x; s4.y += p * v.y; s4.z += p * v.z; s4.w += p * v.w;
        }
        float* orow = ow + ((size_t)win * NTOK + n) * CC + head * HD + dq * 4;
        orow[0] = s4.x; orow[1] = s4.y; orow[2] = s4.z; orow[3] = s4.w;
    }
}

// ---------------- launch ----------------
extern "C" void kernel_launch(void* const* d_in, const int* in_sizes, int n_in,
                              void* d_out, int out_size)
{
    const float* x      = (const float*)d_in[0];
    const float* qkv_w  = (const float*)d_in[1];
    const float* qkv_b  = (const float*)d_in[2];
    const float* proj_w = (const float*)d_in[3];
    const float* proj_b = (const float*)d_in[4];
    const float* rpb    = (const float*)d_in[5];
    const float* n1g    = (const float*)d_in[6];
    const float* n1b    = (const float*)d_in[7];
    const float* n2g    = (const float*)d_in[8];
    const float* n2b    = (const float*)d_in[9];
    const float* fc1_w  = (const float*)d_in[10];
    const float* fc1_b  = (const float*)d_in[11];
    const float* fc2_w  = (const float*)d_in[12];
    const float* fc2_b  = (const float*)d_in[13];
    float* out = (float*)d_out;

    float *xw, *qkv, *ow, *y, *ln2, *mid; int* dmap;
    cudaGetSymbolAddress((void**)&xw,   g_xw);
    cudaGetSymbolAddress((void**)&qkv,  g_qkv);
    cudaGetSymbolAddress((void**)&ow,   g_ow);
    cudaGetSymbolAddress((void**)&y,    g_y);
    cudaGetSymbolAddress((void**)&ln2,  g_ln2);
    cudaGetSymbolAddress((void**)&mid,  g_mid);
    cudaGetSymbolAddress((void**)&dmap, g_dmap);

    cudaFuncSetAttribute(mma_gemm, cudaFuncAttributeMaxDynamicSharedMemorySize, SMEM_BYTES);

    // 1. LN1 + shift + window partition
    ln_kernel<<<TOK, 128>>>(x, n1g, n1b, xw, 1);

    // 2. QKV: (50176,384) @ (384,1152)
    mma_gemm<<<dim3((3 * CC) / GBN, TOK / GBM), 256, SMEM_BYTES>>>(
        xw, qkv_w, qkv_b, qkv, nullptr, nullptr, TOK, 3 * CC, CC, 0);

    // 3. Windowed attention
    attn_kernel<<<dim3(NHD, NWINS), 256>>>(rpb, ow);

    // 4. Proj + window reverse + residual
    mma_gemm<<<dim3(CC / GBN, TOK / GBM), 256, SMEM_BYTES>>>(
        ow, proj_w, proj_b, y, x, dmap, TOK, CC, CC, 0);

    // 5. LN2
    ln_kernel<<<TOK, 128>>>(y, n2g, n2b, ln2, 0);

    // 6. FC1 + GELU: (50176,384) @ (384,1536)
    mma_gemm<<<dim3(HID / GBN, TOK / GBM), 256, SMEM_BYTES>>>(
        ln2, fc1_w, fc1_b, mid, nullptr, nullptr, TOK, HID, CC, 1);

    // 7. FC2 + residual: (50176,1536) @ (1536,384)
    mma_gemm<<<dim3(CC / GBN, TOK / GBM), 256, SMEM_BYTES>>>(
        mid, fc2_w, fc2_b, out, y, nullptr, TOK, CC, HID, 0);
}